// round 1
// baseline (speedup 1.0000x reference)
#include <cuda_runtime.h>
#include <math.h>
#include <stdint.h>

// Problem dims (fixed by the dataset)
#define BMAX 16384
#define D0 1024
#define D1 1024
#define D2 512
#define DEG 5
#define KF 6                    // features per input dim: T1..T5, raw
#define K1 (D0*KF)              // 6144
#define K2 (D1*KF)              // 6144
#define LN_EPS 1e-5f

// ---------------- scratch (device globals; no allocations allowed) ----------
__device__ float g_W1[(size_t)D1*K1];       // 25 MB
__device__ float g_W2[(size_t)D2*K2];       // 12.6 MB
__device__ float g_biasE1[D1];
__device__ float g_biasE2[D2];
__device__ float g_A[(size_t)BMAX*K1];      // 402 MB features (reused for both layers)
__device__ float g_Y1[(size_t)BMAX*D1];     // 67 MB

// ---------------- helpers ---------------------------------------------------
// Accurate tanh independent of -use_fast_math lowering of tanhf.
// abs err ~1e-7 (MUFU.EX2 rel err ~2^-22).
__device__ __forceinline__ float tanh_acc(float x) {
    float ax = fminf(fabsf(x), 10.0f);
    float e  = __expf(2.0f * ax);
    float r  = (e - 1.0f) / (e + 1.0f);
    return copysignf(r, x);
}

__device__ __forceinline__ float blockReduceSum(float v, float* red) {
    int lane = threadIdx.x & 31, w = threadIdx.x >> 5;
    #pragma unroll
    for (int o = 16; o; o >>= 1) v += __shfl_xor_sync(0xffffffffu, v, o);
    __syncthreads();                 // protect red against reuse from prior call
    if (lane == 0) red[w] = v;
    __syncthreads();
    int nw = blockDim.x >> 5;
    float t = (lane < nw) ? red[lane] : 0.0f;
    #pragma unroll
    for (int o = 4; o; o >>= 1) t += __shfl_xor_sync(0xffffffffu, t, o);
    return __shfl_sync(0xffffffffu, t, 0);
}

// ---------------- weight packing -------------------------------------------
// W[o, k*I + i]: k=0..4 -> coeff[o,i,k+1], k=5 -> base_w[o,i]
__global__ void pack_w_kernel(const float* __restrict__ coeff,
                              const float* __restrict__ basew,
                              float* __restrict__ W, int O, int I) {
    int idx = blockIdx.x * blockDim.x + threadIdx.x;
    if (idx >= O * I) return;
    int o = idx / I, i = idx - o * I;
    const float* c = coeff + ((size_t)o * I + i) * (DEG + 1);
    float* w = W + (size_t)o * (I * KF);
    #pragma unroll
    for (int k = 0; k < 5; k++) w[k * I + i] = c[k + 1];
    w[5 * I + i] = basew[(size_t)o * I + i];
}

// biasE[o] = bias[o] + sum_i coeff[o,i,0]   (the T0 == 1 term)
__global__ void bias_eff_kernel(const float* __restrict__ coeff,
                                const float* __restrict__ bias,
                                float* __restrict__ be, int I) {
    __shared__ float red[32];
    int o = blockIdx.x;
    float s = 0.0f;
    for (int i = threadIdx.x; i < I; i += blockDim.x)
        s += coeff[((size_t)o * I + i) * (DEG + 1)];
    float tot = blockReduceSum(s, red);
    if (threadIdx.x == 0) be[o] = bias[o] + tot;
}

// ---------------- layer-1 feature expansion --------------------------------
// t1 = tanh(x) (input normalization), t2 = tanh(t1) (cheb arg)
// A[b, k*D0 + i] = T_{k+1}(t2) for k=0..4 ; A[b, 5*D0 + i] = t1
__global__ void feat1_kernel(const float* __restrict__ x, float* __restrict__ A, int B) {
    int idx = blockIdx.x * blockDim.x + threadIdx.x;
    if (idx >= B * D0) return;
    int b = idx / D0, i = idx - b * D0;
    float t1 = tanh_acc(x[idx]);
    float t2 = tanh_acc(t1);
    float* a = A + (size_t)b * K1;
    float T1 = t2;
    float T2 = 2.0f * t2 * t2 - 1.0f;
    float T3 = 2.0f * t2 * T2 - T1;
    float T4 = 2.0f * t2 * T3 - T2;
    float T5 = 2.0f * t2 * T4 - T3;
    a[0 * D0 + i] = T1;
    a[1 * D0 + i] = T2;
    a[2 * D0 + i] = T3;
    a[3 * D0 + i] = T4;
    a[4 * D0 + i] = T5;
    a[5 * D0 + i] = t1;
}

// ---------------- fused LayerNorm + SiLU + layer-2 features -----------------
__global__ void ln_silu_feat_kernel(const float* __restrict__ Y,
                                    const float* __restrict__ gamma,
                                    const float* __restrict__ beta,
                                    float* __restrict__ A) {
    __shared__ float red[32];
    int b = blockIdx.x;
    const float* y = Y + (size_t)b * D1;
    float v[4];
    #pragma unroll
    for (int c = 0; c < 4; c++) v[c] = y[threadIdx.x + c * 256];
    float s = v[0] + v[1] + v[2] + v[3];
    float mu = blockReduceSum(s, red) * (1.0f / (float)D1);
    float q = 0.0f;
    #pragma unroll
    for (int c = 0; c < 4; c++) { float d = v[c] - mu; q += d * d; }
    float var = blockReduceSum(q, red) * (1.0f / (float)D1);
    float rs = rsqrtf(var + LN_EPS);
    float* a = A + (size_t)b * K2;
    #pragma unroll
    for (int c = 0; c < 4; c++) {
        int i = threadIdx.x + c * 256;
        float hn = (v[c] - mu) * rs * gamma[i] + beta[i];
        float h  = hn * (1.0f / (1.0f + __expf(-hn)));   // SiLU
        float t  = tanh_acc(h);
        float T1 = t;
        float T2 = 2.0f * t * t - 1.0f;
        float T3 = 2.0f * t * T2 - T1;
        float T4 = 2.0f * t * T3 - T2;
        float T5 = 2.0f * t * T4 - T3;
        a[0 * D1 + i] = T1;
        a[1 * D1 + i] = T2;
        a[2 * D1 + i] = T3;
        a[3 * D1 + i] = T4;
        a[4 * D1 + i] = T5;
        a[5 * D1 + i] = h;
    }
}

// ---------------- tiled SGEMM: C[M,N] = A[M,K] * W[N,K]^T + biasE -----------
#define BM 128
#define BN 128
#define BK 16
#define LDS_PAD 132

__global__ __launch_bounds__(256, 2)
void sgemm_tn_kernel(const float* __restrict__ A, const float* __restrict__ W,
                     const float* __restrict__ biasE, float* __restrict__ C,
                     int M, int N, int K) {
    __shared__ float As[2][BK * LDS_PAD];
    __shared__ float Bs[2][BK * LDS_PAD];

    int tid = threadIdx.x;
    int tx = tid & 15, ty = tid >> 4;
    int bn = blockIdx.x, bm = blockIdx.y;

    const float* Ag = A + (size_t)bm * BM * K;
    const float* Wg = W + (size_t)bn * BN * K;

    float acc[8][8];
    #pragma unroll
    for (int i = 0; i < 8; i++)
        #pragma unroll
        for (int j = 0; j < 8; j++) acc[i][j] = 0.0f;

    float4 pa[2], pb[2];
    int r_[2], kv_[2];
    #pragma unroll
    for (int j = 0; j < 2; j++) {
        int idx = tid * 2 + j;
        r_[j] = idx >> 2;
        kv_[j] = idx & 3;
    }

    // prefetch tile 0
    #pragma unroll
    for (int j = 0; j < 2; j++) {
        pa[j] = *(const float4*)(Ag + (size_t)r_[j] * K + kv_[j] * 4);
        pb[j] = *(const float4*)(Wg + (size_t)r_[j] * K + kv_[j] * 4);
    }
    // store tile 0
    #pragma unroll
    for (int j = 0; j < 2; j++) {
        float va[4] = {pa[j].x, pa[j].y, pa[j].z, pa[j].w};
        float vb[4] = {pb[j].x, pb[j].y, pb[j].z, pb[j].w};
        #pragma unroll
        for (int c = 0; c < 4; c++) {
            As[0][(kv_[j] * 4 + c) * LDS_PAD + r_[j]] = va[c];
            Bs[0][(kv_[j] * 4 + c) * LDS_PAD + r_[j]] = vb[c];
        }
    }
    __syncthreads();

    int nt = K / BK;
    int cur = 0;
    for (int t = 0; t < nt; t++) {
        if (t + 1 < nt) {
            int k0 = (t + 1) * BK;
            #pragma unroll
            for (int j = 0; j < 2; j++) {
                pa[j] = *(const float4*)(Ag + (size_t)r_[j] * K + k0 + kv_[j] * 4);
                pb[j] = *(const float4*)(Wg + (size_t)r_[j] * K + k0 + kv_[j] * 4);
            }
        }
        #pragma unroll
        for (int k = 0; k < BK; k++) {
            float af[8], bf[8];
            *(float4*)(af)     = *(const float4*)&As[cur][k * LDS_PAD + ty * 8];
            *(float4*)(af + 4) = *(const float4*)&As[cur][k * LDS_PAD + ty * 8 + 4];
            *(float4*)(bf)     = *(const float4*)&Bs[cur][k * LDS_PAD + tx * 8];
            *(float4*)(bf + 4) = *(const float4*)&Bs[cur][k * LDS_PAD + tx * 8 + 4];
            #pragma unroll
            for (int im = 0; im < 8; im++)
                #pragma unroll
                for (int in = 0; in < 8; in++)
                    acc[im][in] += af[im] * bf[in];
        }
        if (t + 1 < nt) {
            int nxt = cur ^ 1;
            #pragma unroll
            for (int j = 0; j < 2; j++) {
                float va[4] = {pa[j].x, pa[j].y, pa[j].z, pa[j].w};
                float vb[4] = {pb[j].x, pb[j].y, pb[j].z, pb[j].w};
                #pragma unroll
                for (int c = 0; c < 4; c++) {
                    As[nxt][(kv_[j] * 4 + c) * LDS_PAD + r_[j]] = va[c];
                    Bs[nxt][(kv_[j] * 4 + c) * LDS_PAD + r_[j]] = vb[c];
                }
            }
            __syncthreads();
            cur = nxt;
        }
    }

    float bb[8];
    #pragma unroll
    for (int in = 0; in < 8; in++) bb[in] = biasE[bn * BN + tx * 8 + in];

    #pragma unroll
    for (int im = 0; im < 8; im++) {
        float o0[4], o1[4];
        #pragma unroll
        for (int in = 0; in < 4; in++) o0[in] = acc[im][in] + bb[in];
        #pragma unroll
        for (int in = 0; in < 4; in++) o1[in] = acc[im][in + 4] + bb[in + 4];
        size_t row = (size_t)(bm * BM + ty * 8 + im);
        *(float4*)(C + row * N + bn * BN + tx * 8)     = *(float4*)o0;
        *(float4*)(C + row * N + bn * BN + tx * 8 + 4) = *(float4*)o1;
    }
}

// ---------------- launch ----------------------------------------------------
extern "C" void kernel_launch(void* const* d_in, const int* in_sizes, int n_in,
                              void* d_out, int out_size) {
    const float* x      = (const float*)d_in[0];
    const float* coeff1 = (const float*)d_in[1];
    const float* basew1 = (const float*)d_in[2];
    const float* bias1  = (const float*)d_in[3];
    const float* gamma  = (const float*)d_in[4];
    const float* beta   = (const float*)d_in[5];
    const float* coeff2 = (const float*)d_in[6];
    const float* basew2 = (const float*)d_in[7];
    const float* bias2  = (const float*)d_in[8];

    int B = in_sizes[0] / D0;

    float *pW1, *pW2, *pB1, *pB2, *pA, *pY1;
    cudaGetSymbolAddress((void**)&pW1, g_W1);
    cudaGetSymbolAddress((void**)&pW2, g_W2);
    cudaGetSymbolAddress((void**)&pB1, g_biasE1);
    cudaGetSymbolAddress((void**)&pB2, g_biasE2);
    cudaGetSymbolAddress((void**)&pA,  g_A);
    cudaGetSymbolAddress((void**)&pY1, g_Y1);

    // weight packing + effective biases
    pack_w_kernel<<<(D1 * D0 + 255) / 256, 256>>>(coeff1, basew1, pW1, D1, D0);
    pack_w_kernel<<<(D2 * D1 + 255) / 256, 256>>>(coeff2, basew2, pW2, D2, D1);
    bias_eff_kernel<<<D1, 256>>>(coeff1, bias1, pB1, D0);
    bias_eff_kernel<<<D2, 256>>>(coeff2, bias2, pB2, D1);

    // layer 1
    feat1_kernel<<<(B * D0 + 255) / 256, 256>>>(x, pA, B);
    sgemm_tn_kernel<<<dim3(D1 / BN, B / BM), 256>>>(pA, pW1, pB1, pY1, B, D1, K1);

    // LN + SiLU + layer-2 features
    ln_silu_feat_kernel<<<B, 256>>>(pY1, gamma, beta, pA);

    // layer 2 -> output
    sgemm_tn_kernel<<<dim3(D2 / BN, B / BM), 256>>>(pA, pW2, pB2, (float*)d_out, B, D2, K2);
}

// round 8
// speedup vs baseline: 3.0294x; 3.0294x over previous
#include <cuda_runtime.h>
#include <cuda.h>
#include <cuda_fp16.h>
#include <math.h>
#include <stdint.h>

// ---------------- problem dims ----------------
#define D0 1024
#define D1 1024
#define D2 512
#define DEG 5
#define KC 6144            // K per "copy" = 6*1024
#define K2X 12288          // hi|lo concat for weights
#define NT 288             // 3*6144/64
#define SEGI 96            // iters per segment
#define LN_EPS 1e-5f
#define BMAX 16384

#define BM 128
#define BN 128
#define BK 64
#define STAGES 3
#define STAGE_BYTES 32768          // 16KB A + 16KB B
#define SMEM_TOTAL (1024 + STAGES*STAGE_BYTES)

// ---------------- device scratch (no allocs allowed) ----------------
__device__ __half g_Ahi[(size_t)BMAX * KC];
__device__ __half g_Alo[(size_t)BMAX * KC];
__device__ __half g_W1[(size_t)D1 * K2X];     // [hi | lo]
__device__ __half g_W2[(size_t)D2 * K2X];
__device__ float g_biasE1[D1];
__device__ float g_biasE2[D2];
__device__ float g_Y1[(size_t)BMAX * D1];

// ---------------- PTX helpers (sm_90-level only; NO tcgen05) ----------------
__device__ __forceinline__ uint32_t smem_u32(const void* p) {
    uint32_t a;
    asm("{ .reg .u64 t; cvta.to.shared.u64 t, %1; cvt.u32.u64 %0, t; }" : "=r"(a) : "l"(p));
    return a;
}
#define MBAR_INIT(a, c) asm volatile("mbarrier.init.shared.b64 [%0], %1;" :: "r"(a), "r"(c) : "memory")
#define MBAR_EXPECT_TX(a, b) asm volatile("mbarrier.arrive.expect_tx.shared.b64 _, [%0], %1;" :: "r"(a), "r"(b) : "memory")
#define MBAR_ARRIVE(a) asm volatile("mbarrier.arrive.shared.b64 _, [%0];" :: "r"(a) : "memory")

#define MBAR_WAIT(addr, ph) do { \
    uint32_t _m = (addr), _p = (ph), _d; \
    asm volatile("{\n\t.reg .pred p;\n\tmbarrier.try_wait.parity.acquire.cta.shared::cta.b64 p, [%1], %2;\n\tselp.b32 %0, 1, 0, p;\n\t}" \
        : "=r"(_d) : "r"(_m), "r"(_p) : "memory"); \
    if (!_d) { asm volatile("{\n\t.reg .pred P1;\n\tWL_%=:\n\tmbarrier.try_wait.parity.acquire.cta.shared::cta.b64 P1, [%0], %1, 0x989680;\n\t@P1 bra.uni WD_%=;\n\tbra.uni WL_%=;\n\tWD_%=:\n\t}" \
        :: "r"(_m), "r"(_p) : "memory"); } \
} while (0)

#define MBAR_WAIT_RELAXED(addr, ph) do { \
    uint32_t _m = (addr), _p = (ph), _d; \
    asm volatile("{\n\t.reg .pred p;\n\tmbarrier.try_wait.parity.relaxed.cta.shared::cta.b64 p, [%1], %2, 0x989680;\n\tselp.b32 %0, 1, 0, p;\n\t}" \
        : "=r"(_d) : "r"(_m), "r"(_p) : "memory"); \
    if (!_d) { asm volatile("{\n\t.reg .pred P1;\n\tWL_%=:\n\tmbarrier.try_wait.parity.relaxed.cta.shared::cta.b64 P1, [%0], %1, 0x989680;\n\t@P1 bra.uni WD_%=;\n\tbra.uni WL_%=;\n\tWD_%=:\n\t}" \
        :: "r"(_m), "r"(_p) : "memory"); } \
} while (0)

__device__ __forceinline__ void tma2d(uint32_t dst, const CUtensorMap* map, int x, int y, uint32_t mbar) {
    asm volatile("cp.async.bulk.tensor.2d.shared::cta.global.tile.mbarrier::complete_tx::bytes [%0], [%1, {%2, %3}], [%4];"
        :: "r"(dst), "l"(map), "r"(x), "r"(y), "r"(mbar) : "memory");
}

__device__ __forceinline__ void ldsm4(uint32_t* r, uint32_t addr) {
    asm volatile("ldmatrix.sync.aligned.m8n8.x4.shared.b16 {%0,%1,%2,%3}, [%4];"
        : "=r"(r[0]), "=r"(r[1]), "=r"(r[2]), "=r"(r[3]) : "r"(addr));
}

__device__ __forceinline__ void mma16816(float* c, const uint32_t* a, const uint32_t* b) {
    asm volatile("mma.sync.aligned.m16n8k16.row.col.f32.f16.f16.f32 "
                 "{%0,%1,%2,%3},{%4,%5,%6,%7},{%8,%9},{%0,%1,%2,%3};"
        : "+f"(c[0]), "+f"(c[1]), "+f"(c[2]), "+f"(c[3])
        : "r"(a[0]), "r"(a[1]), "r"(a[2]), "r"(a[3]), "r"(b[0]), "r"(b[1]));
}

// ---------------- math helpers ----------------
__device__ __forceinline__ float tanh_acc(float x) {
    float ax = fminf(fabsf(x), 10.0f);
    float e = __expf(2.0f * ax);
    float r = (e - 1.0f) / (e + 1.0f);
    return copysignf(r, x);
}
__device__ __forceinline__ void split_store(float v, __half* hi, __half* lo) {
    __half h = __float2half_rn(v);
    *hi = h;
    *lo = __float2half_rn(v - __half2float(h));
}
__device__ __forceinline__ float blockReduceSum(float v, float* red) {
    int lane = threadIdx.x & 31, w = threadIdx.x >> 5;
    #pragma unroll
    for (int o = 16; o; o >>= 1) v += __shfl_xor_sync(0xffffffffu, v, o);
    __syncthreads();
    if (lane == 0) red[w] = v;
    __syncthreads();
    float t = (lane < (blockDim.x >> 5)) ? red[lane] : 0.0f;
    #pragma unroll
    for (int o = 4; o; o >>= 1) t += __shfl_xor_sync(0xffffffffu, t, o);
    return __shfl_sync(0xffffffffu, t, 0);
}

// ---------------- prep kernels ----------------
__global__ void pack_w_kernel(const float* __restrict__ coeff, const float* __restrict__ basew,
                              __half* __restrict__ W, int O) {
    int idx = blockIdx.x * blockDim.x + threadIdx.x;
    if (idx >= O * 1024) return;
    int o = idx >> 10, i = idx & 1023;
    const float* c = coeff + ((size_t)o * 1024 + i) * (DEG + 1);
    __half* w = W + (size_t)o * K2X;
    #pragma unroll
    for (int k = 0; k < 5; k++) {
        float v = c[k + 1];
        split_store(v, &w[k * 1024 + i], &w[KC + k * 1024 + i]);
    }
    float v = basew[(size_t)o * 1024 + i];
    split_store(v, &w[5 * 1024 + i], &w[KC + 5 * 1024 + i]);
}

__global__ void bias_eff_kernel(const float* __restrict__ coeff, const float* __restrict__ bias,
                                float* __restrict__ be, int I) {
    __shared__ float red[32];
    int o = blockIdx.x;
    float s = 0.0f;
    for (int i = threadIdx.x; i < I; i += blockDim.x)
        s += coeff[((size_t)o * I + i) * (DEG + 1)];
    float tot = blockReduceSum(s, red);
    if (threadIdx.x == 0) be[o] = bias[o] + tot;
}

__global__ void feat1_kernel(const float* __restrict__ x,
                             __half* __restrict__ Ah, __half* __restrict__ Al, int B) {
    int idx = blockIdx.x * blockDim.x + threadIdx.x;
    if (idx >= B * D0) return;
    int b = idx >> 10, i = idx & 1023;
    float t1 = tanh_acc(x[idx]);
    float t2 = tanh_acc(t1);
    float T1 = t2, T2 = 2.f * t2 * t2 - 1.f;
    float T3 = 2.f * t2 * T2 - T1, T4 = 2.f * t2 * T3 - T2, T5 = 2.f * t2 * T4 - T3;
    __half* ah = Ah + (size_t)b * KC;
    __half* al = Al + (size_t)b * KC;
    split_store(T1, &ah[0 * D0 + i], &al[0 * D0 + i]);
    split_store(T2, &ah[1 * D0 + i], &al[1 * D0 + i]);
    split_store(T3, &ah[2 * D0 + i], &al[2 * D0 + i]);
    split_store(T4, &ah[3 * D0 + i], &al[3 * D0 + i]);
    split_store(T5, &ah[4 * D0 + i], &al[4 * D0 + i]);
    split_store(t1, &ah[5 * D0 + i], &al[5 * D0 + i]);
}

__global__ void ln_silu_feat_kernel(const float* __restrict__ Y,
                                    const float* __restrict__ gamma, const float* __restrict__ beta,
                                    __half* __restrict__ Ah, __half* __restrict__ Al) {
    __shared__ float red[32];
    int b = blockIdx.x;
    const float* y = Y + (size_t)b * D1;
    float v[4];
    #pragma unroll
    for (int c = 0; c < 4; c++) v[c] = y[threadIdx.x + c * 256];
    float mu = blockReduceSum(v[0] + v[1] + v[2] + v[3], red) * (1.0f / (float)D1);
    float q = 0.0f;
    #pragma unroll
    for (int c = 0; c < 4; c++) { float d = v[c] - mu; q += d * d; }
    float var = blockReduceSum(q, red) * (1.0f / (float)D1);
    float rs = rsqrtf(var + LN_EPS);
    __half* ah = Ah + (size_t)b * KC;
    __half* al = Al + (size_t)b * KC;
    #pragma unroll
    for (int c = 0; c < 4; c++) {
        int i = threadIdx.x + c * 256;
        float hn = (v[c] - mu) * rs * gamma[i] + beta[i];
        float h = hn * (1.0f / (1.0f + __expf(-hn)));
        float t = tanh_acc(h);
        float T1 = t, T2 = 2.f * t * t - 1.f;
        float T3 = 2.f * t * T2 - T1, T4 = 2.f * t * T3 - T2, T5 = 2.f * t * T4 - T3;
        split_store(T1, &ah[0 * D1 + i], &al[0 * D1 + i]);
        split_store(T2, &ah[1 * D1 + i], &al[1 * D1 + i]);
        split_store(T3, &ah[2 * D1 + i], &al[2 * D1 + i]);
        split_store(T4, &ah[3 * D1 + i], &al[3 * D1 + i]);
        split_store(T5, &ah[4 * D1 + i], &al[4 * D1 + i]);
        split_store(h,  &ah[5 * D1 + i], &al[5 * D1 + i]);
    }
}

// ---------------- HMMA GEMM: C[M,N] = A[M,K']*W[N,K']^T + biasE ------------
// 3-term fp16 split over 3 K-segments; BM=128 BN=128 BK=64, 3-stage TMA pipe,
// mma.sync.m16n8k16 with f32 accumulators in registers.
#define SM_FULL(s)  (8u + 8u * (s))
#define SM_EMPTY(s) (40u + 8u * (s))
#define SM_A(s)     (1024u + (s) * STAGE_BYTES)
#define SM_B(s)     (1024u + (s) * STAGE_BYTES + 16384u)

__global__ __launch_bounds__(256, 2)
void kan_gemm_kernel(const __grid_constant__ CUtensorMap tma_ahi,
                     const __grid_constant__ CUtensorMap tma_alo,
                     const __grid_constant__ CUtensorMap tma_w,
                     const float* __restrict__ biasE,
                     float* __restrict__ C, int ldc) {
    extern __shared__ __align__(1024) char smem[];
    uint32_t sb = smem_u32(smem);
    int tid = threadIdx.x;
    int wid = tid >> 5, lane = tid & 31;
    int m_w = (wid & 3) * 32;        // warp rows within BM
    int n_w = (wid >> 2) * 64;       // warp cols within BN

    if (tid == 0) {
        #pragma unroll
        for (int s = 0; s < STAGES; s++) {
            MBAR_INIT(sb + SM_FULL(s), 1);
            MBAR_INIT(sb + SM_EMPTY(s), 8);
        }
    }
    __syncthreads();

    const int m0 = blockIdx.y * BM;
    const int n0 = blockIdx.x * BN;

    // prologue: issue stages 0 and 1
    if (tid == 0) {
        #pragma unroll
        for (int ti = 0; ti < STAGES - 1; ti++) {
            MBAR_EXPECT_TX(sb + SM_FULL(ti), STAGE_BYTES);
            tma2d(sb + SM_A(ti), &tma_ahi, ti * BK, m0, sb + SM_FULL(ti));
            tma2d(sb + SM_B(ti), &tma_w, ti * BK, n0, sb + SM_FULL(ti));
        }
    }

    float acc[2][8][4];
    #pragma unroll
    for (int mt = 0; mt < 2; mt++)
        #pragma unroll
        for (int nt = 0; nt < 8; nt++)
            #pragma unroll
            for (int j = 0; j < 4; j++) acc[mt][nt][j] = 0.0f;

    // per-thread ldmatrix addressing (SW128 swizzle: xor term constant/thread)
    int rbase = (lane & 7) + ((lane >> 3) & 1) * 8;
    int hb = ((lane >> 4) & 1) * 16;
    uint32_t xorv = (uint32_t)((lane & 7) << 4);
    uint32_t aoffA = (uint32_t)(m_w + rbase) * 128u;
    uint32_t aoffB = (uint32_t)(n_w + rbase) * 128u;

    int s = 0, pf = 0, ep = 0;
    for (int t = 0; t < NT; t++) {
        MBAR_WAIT(sb + SM_FULL(s), pf);

        if (tid == 0 && t + STAGES - 1 < NT) {
            int ti = t + STAGES - 1;
            int sp = ti % STAGES;
            if (ti >= STAGES) {
                MBAR_WAIT_RELAXED(sb + SM_EMPTY(sp), ep);
                if (sp == STAGES - 1) ep ^= 1;
            }
            MBAR_EXPECT_TX(sb + SM_FULL(sp), STAGE_BYTES);
            int seg = ti / SEGI;
            int tk = (ti - seg * SEGI) * BK;
            const CUtensorMap* am = (seg < 2) ? &tma_ahi : &tma_alo;
            int wx = (seg == 1) ? (KC + tk) : tk;
            tma2d(sb + SM_A(sp), am, tk, m0, sb + SM_FULL(sp));
            tma2d(sb + SM_B(sp), &tma_w, wx, n0, sb + SM_FULL(sp));
        }

        uint32_t sA = sb + SM_A(s);
        uint32_t sBt = sb + SM_B(s);
        #pragma unroll
        for (int ks = 0; ks < 4; ks++) {
            uint32_t col = ((uint32_t)(ks * 32 + hb)) ^ xorv;
            uint32_t a[2][4];
            ldsm4(a[0], sA + aoffA + col);
            ldsm4(a[1], sA + aoffA + 2048u + col);
            uint32_t b[8][2];
            #pragma unroll
            for (int g = 0; g < 4; g++) {
                uint32_t r[4];
                ldsm4(r, sBt + aoffB + (uint32_t)g * 2048u + col);
                b[2 * g][0] = r[0]; b[2 * g][1] = r[2];
                b[2 * g + 1][0] = r[1]; b[2 * g + 1][1] = r[3];
            }
            #pragma unroll
            for (int mt = 0; mt < 2; mt++)
                #pragma unroll
                for (int nt = 0; nt < 8; nt++)
                    mma16816(acc[mt][nt], a[mt], b[nt]);
        }
        if (lane == 0) MBAR_ARRIVE(sb + SM_EMPTY(s));
        s++;
        if (s == STAGES) { s = 0; pf ^= 1; }
    }

    // epilogue: register fragments -> global, + bias
    const float* bptr = biasE + n0 + n_w;
    #pragma unroll
    for (int mt = 0; mt < 2; mt++) {
        int r0 = m0 + m_w + mt * 16 + (lane >> 2);
        float* c0 = C + (size_t)r0 * ldc + n0 + n_w;
        float* c1 = c0 + 8 * (size_t)ldc;
        #pragma unroll
        for (int nt = 0; nt < 8; nt++) {
            int cidx = nt * 8 + (lane & 3) * 2;
            float bx = bptr[cidx], by = bptr[cidx + 1];
            float2 v0 = make_float2(acc[mt][nt][0] + bx, acc[mt][nt][1] + by);
            float2 v1 = make_float2(acc[mt][nt][2] + bx, acc[mt][nt][3] + by);
            *(float2*)(c0 + cidx) = v0;
            *(float2*)(c1 + cidx) = v1;
        }
    }
}

// ---------------- host ----------------
typedef CUresult (*PFN_encodeTiled)(CUtensorMap*, CUtensorMapDataType, cuuint32_t, void*,
                                    const cuuint64_t*, const cuuint64_t*, const cuuint32_t*, const cuuint32_t*,
                                    CUtensorMapInterleave, CUtensorMapSwizzle, CUtensorMapL2promotion,
                                    CUtensorMapFloatOOBfill);

static void encode_2d(PFN_encodeTiled enc, CUtensorMap* m, void* base,
                      uint64_t d0, uint64_t d1, uint32_t b0, uint32_t b1) {
    cuuint64_t dims[2] = {d0, d1};
    cuuint64_t strides[1] = {d0 * 2};   // fp16 row pitch
    cuuint32_t box[2] = {b0, b1};
    cuuint32_t es[2] = {1, 1};
    enc(m, CU_TENSOR_MAP_DATA_TYPE_FLOAT16, 2, base, dims, strides, box, es,
        CU_TENSOR_MAP_INTERLEAVE_NONE, CU_TENSOR_MAP_SWIZZLE_128B,
        CU_TENSOR_MAP_L2_PROMOTION_L2_128B, CU_TENSOR_MAP_FLOAT_OOB_FILL_NONE);
}

extern "C" void kernel_launch(void* const* d_in, const int* in_sizes, int n_in,
                              void* d_out, int out_size) {
    const float* x      = (const float*)d_in[0];
    const float* coeff1 = (const float*)d_in[1];
    const float* basew1 = (const float*)d_in[2];
    const float* bias1  = (const float*)d_in[3];
    const float* gamma  = (const float*)d_in[4];
    const float* beta   = (const float*)d_in[5];
    const float* coeff2 = (const float*)d_in[6];
    const float* basew2 = (const float*)d_in[7];
    const float* bias2  = (const float*)d_in[8];

    int B = in_sizes[0] / D0;

    void *pAh, *pAl, *pW1, *pW2, *pB1, *pB2, *pY1;
    cudaGetSymbolAddress(&pAh, g_Ahi);
    cudaGetSymbolAddress(&pAl, g_Alo);
    cudaGetSymbolAddress(&pW1, g_W1);
    cudaGetSymbolAddress(&pW2, g_W2);
    cudaGetSymbolAddress(&pB1, g_biasE1);
    cudaGetSymbolAddress(&pB2, g_biasE2);
    cudaGetSymbolAddress(&pY1, g_Y1);

    PFN_encodeTiled enc = nullptr;
    cudaDriverEntryPointQueryResult qr;
    cudaGetDriverEntryPointByVersion("cuTensorMapEncodeTiled", (void**)&enc, 12000,
                                     cudaEnableDefault, &qr);

    CUtensorMap tma_ahi, tma_alo, tma_w1, tma_w2;
    encode_2d(enc, &tma_ahi, pAh, KC, (uint64_t)B, BK, BM);
    encode_2d(enc, &tma_alo, pAl, KC, (uint64_t)B, BK, BM);
    encode_2d(enc, &tma_w1, pW1, K2X, D1, BK, BN);
    encode_2d(enc, &tma_w2, pW2, K2X, D2, BK, BN);

    cudaFuncSetAttribute(kan_gemm_kernel, cudaFuncAttributeMaxDynamicSharedMemorySize, SMEM_TOTAL);

    // prep
    pack_w_kernel<<<(D1 * 1024 + 255) / 256, 256>>>(coeff1, basew1, (__half*)pW1, D1);
    pack_w_kernel<<<(D2 * 1024 + 255) / 256, 256>>>(coeff2, basew2, (__half*)pW2, D2);
    bias_eff_kernel<<<D1, 256>>>(coeff1, bias1, (float*)pB1, D0);
    bias_eff_kernel<<<D2, 256>>>(coeff2, bias2, (float*)pB2, D1);

    // layer 1
    feat1_kernel<<<(B * D0 + 255) / 256, 256>>>(x, (__half*)pAh, (__half*)pAl, B);
    kan_gemm_kernel<<<dim3(D1 / BN, B / BM), 256, SMEM_TOTAL>>>(
        tma_ahi, tma_alo, tma_w1, (const float*)pB1, (float*)pY1, D1);

    // LN + SiLU + layer-2 features
    ln_silu_feat_kernel<<<B, 256>>>((const float*)pY1, gamma, beta,
                                    (__half*)pAh, (__half*)pAl);

    // layer 2 -> output
    kan_gemm_kernel<<<dim3(D2 / BN, B / BM), 256, SMEM_TOTAL>>>(
        tma_ahi, tma_alo, tma_w2, (const float*)pB2, (float*)d_out, D2);
}

// round 9
// speedup vs baseline: 4.3926x; 1.4500x over previous
#include <cuda_runtime.h>
#include <cuda.h>
#include <cuda_fp16.h>
#include <math.h>
#include <stdint.h>

// ---------------- problem dims ----------------
#define D0 1024
#define D1 1024
#define D2 512
#define DEG 5
#define KC 6144            // K per "copy" = 6*1024
#define K2X 12288          // hi|lo concat for weights
#define NT 192             // 2 segments * 6144/64
#define SEGI 96            // iters per segment
#define LN_EPS 1e-5f
#define BMAX 16384

#define BM 128
#define BN 128
#define BK 64
#define STAGES 3
#define STAGE_BYTES 32768          // 16KB A + 16KB B
#define SMEM_TOTAL (1024 + STAGES*STAGE_BYTES)

// ---------------- device scratch (no allocs allowed) ----------------
__device__ __half g_Ahi[(size_t)BMAX * KC];   // 201 MB
__device__ __half g_W1[(size_t)D1 * K2X];     // [hi | lo]
__device__ __half g_W2[(size_t)D2 * K2X];
__device__ float g_biasE1[D1];
__device__ float g_biasE2[D2];
__device__ float g_Y1[(size_t)BMAX * D1];

// ---------------- PTX helpers (sm_90-level only; NO tcgen05) ----------------
__device__ __forceinline__ uint32_t smem_u32(const void* p) {
    uint32_t a;
    asm("{ .reg .u64 t; cvta.to.shared.u64 t, %1; cvt.u32.u64 %0, t; }" : "=r"(a) : "l"(p));
    return a;
}
#define MBAR_INIT(a, c) asm volatile("mbarrier.init.shared.b64 [%0], %1;" :: "r"(a), "r"(c) : "memory")
#define MBAR_EXPECT_TX(a, b) asm volatile("mbarrier.arrive.expect_tx.shared.b64 _, [%0], %1;" :: "r"(a), "r"(b) : "memory")
#define MBAR_ARRIVE(a) asm volatile("mbarrier.arrive.shared.b64 _, [%0];" :: "r"(a) : "memory")

#define MBAR_WAIT(addr, ph) do { \
    uint32_t _m = (addr), _p = (ph), _d; \
    asm volatile("{\n\t.reg .pred p;\n\tmbarrier.try_wait.parity.acquire.cta.shared::cta.b64 p, [%1], %2;\n\tselp.b32 %0, 1, 0, p;\n\t}" \
        : "=r"(_d) : "r"(_m), "r"(_p) : "memory"); \
    if (!_d) { asm volatile("{\n\t.reg .pred P1;\n\tWL_%=:\n\tmbarrier.try_wait.parity.acquire.cta.shared::cta.b64 P1, [%0], %1, 0x989680;\n\t@P1 bra.uni WD_%=;\n\tbra.uni WL_%=;\n\tWD_%=:\n\t}" \
        :: "r"(_m), "r"(_p) : "memory"); } \
} while (0)

#define MBAR_WAIT_RELAXED(addr, ph) do { \
    uint32_t _m = (addr), _p = (ph), _d; \
    asm volatile("{\n\t.reg .pred p;\n\tmbarrier.try_wait.parity.relaxed.cta.shared::cta.b64 p, [%1], %2, 0x989680;\n\tselp.b32 %0, 1, 0, p;\n\t}" \
        : "=r"(_d) : "r"(_m), "r"(_p) : "memory"); \
    if (!_d) { asm volatile("{\n\t.reg .pred P1;\n\tWL_%=:\n\tmbarrier.try_wait.parity.relaxed.cta.shared::cta.b64 P1, [%0], %1, 0x989680;\n\t@P1 bra.uni WD_%=;\n\tbra.uni WL_%=;\n\tWD_%=:\n\t}" \
        :: "r"(_m), "r"(_p) : "memory"); } \
} while (0)

__device__ __forceinline__ void tma2d(uint32_t dst, const CUtensorMap* map, int x, int y, uint32_t mbar) {
    asm volatile("cp.async.bulk.tensor.2d.shared::cta.global.tile.mbarrier::complete_tx::bytes [%0], [%1, {%2, %3}], [%4];"
        :: "r"(dst), "l"(map), "r"(x), "r"(y), "r"(mbar) : "memory");
}

__device__ __forceinline__ void ldsm4(uint32_t* r, uint32_t addr) {
    asm volatile("ldmatrix.sync.aligned.m8n8.x4.shared.b16 {%0,%1,%2,%3}, [%4];"
        : "=r"(r[0]), "=r"(r[1]), "=r"(r[2]), "=r"(r[3]) : "r"(addr));
}

__device__ __forceinline__ void mma16816(float* c, const uint32_t* a, const uint32_t* b) {
    asm volatile("mma.sync.aligned.m16n8k16.row.col.f32.f16.f16.f32 "
                 "{%0,%1,%2,%3},{%4,%5,%6,%7},{%8,%9},{%0,%1,%2,%3};"
        : "+f"(c[0]), "+f"(c[1]), "+f"(c[2]), "+f"(c[3])
        : "r"(a[0]), "r"(a[1]), "r"(a[2]), "r"(a[3]), "r"(b[0]), "r"(b[1]));
}

// ---------------- math helpers ----------------
__device__ __forceinline__ float tanh_acc(float x) {
    float ax = fminf(fabsf(x), 10.0f);
    float e = __expf(2.0f * ax);
    float r = (e - 1.0f) / (e + 1.0f);
    return copysignf(r, x);
}
__device__ __forceinline__ void split_store(float v, __half* hi, __half* lo) {
    __half h = __float2half_rn(v);
    *hi = h;
    *lo = __float2half_rn(v - __half2float(h));
}
__device__ __forceinline__ float blockReduceSum(float v, float* red) {
    int lane = threadIdx.x & 31, w = threadIdx.x >> 5;
    #pragma unroll
    for (int o = 16; o; o >>= 1) v += __shfl_xor_sync(0xffffffffu, v, o);
    __syncthreads();
    if (lane == 0) red[w] = v;
    __syncthreads();
    float t = (lane < (blockDim.x >> 5)) ? red[lane] : 0.0f;
    #pragma unroll
    for (int o = 4; o; o >>= 1) t += __shfl_xor_sync(0xffffffffu, t, o);
    return __shfl_sync(0xffffffffu, t, 0);
}

// ---------------- prep kernels ----------------
__global__ void pack_w_kernel(const float* __restrict__ coeff, const float* __restrict__ basew,
                              __half* __restrict__ W, int O) {
    int idx = blockIdx.x * blockDim.x + threadIdx.x;
    if (idx >= O * 1024) return;
    int o = idx >> 10, i = idx & 1023;
    const float* c = coeff + ((size_t)o * 1024 + i) * (DEG + 1);
    __half* w = W + (size_t)o * K2X;
    #pragma unroll
    for (int k = 0; k < 5; k++) {
        float v = c[k + 1];
        split_store(v, &w[k * 1024 + i], &w[KC + k * 1024 + i]);
    }
    float v = basew[(size_t)o * 1024 + i];
    split_store(v, &w[5 * 1024 + i], &w[KC + 5 * 1024 + i]);
}

__global__ void bias_eff_kernel(const float* __restrict__ coeff, const float* __restrict__ bias,
                                float* __restrict__ be, int I) {
    __shared__ float red[32];
    int o = blockIdx.x;
    float s = 0.0f;
    for (int i = threadIdx.x; i < I; i += blockDim.x)
        s += coeff[((size_t)o * I + i) * (DEG + 1)];
    float tot = blockReduceSum(s, red);
    if (threadIdx.x == 0) be[o] = bias[o] + tot;
}

__global__ void feat1_kernel(const float* __restrict__ x, __half* __restrict__ Ah, int B) {
    int idx = blockIdx.x * blockDim.x + threadIdx.x;
    if (idx >= B * D0) return;
    int b = idx >> 10, i = idx & 1023;
    float t1 = tanh_acc(x[idx]);
    float t2 = tanh_acc(t1);
    float T1 = t2, T2 = 2.f * t2 * t2 - 1.f;
    float T3 = 2.f * t2 * T2 - T1, T4 = 2.f * t2 * T3 - T2, T5 = 2.f * t2 * T4 - T3;
    __half* ah = Ah + (size_t)b * KC;
    ah[0 * D0 + i] = __float2half_rn(T1);
    ah[1 * D0 + i] = __float2half_rn(T2);
    ah[2 * D0 + i] = __float2half_rn(T3);
    ah[3 * D0 + i] = __float2half_rn(T4);
    ah[4 * D0 + i] = __float2half_rn(T5);
    ah[5 * D0 + i] = __float2half_rn(t1);
}

__global__ void ln_silu_feat_kernel(const float* __restrict__ Y,
                                    const float* __restrict__ gamma, const float* __restrict__ beta,
                                    __half* __restrict__ Ah) {
    __shared__ float red[32];
    int b = blockIdx.x;
    const float* y = Y + (size_t)b * D1;
    float v[4];
    #pragma unroll
    for (int c = 0; c < 4; c++) v[c] = y[threadIdx.x + c * 256];
    float mu = blockReduceSum(v[0] + v[1] + v[2] + v[3], red) * (1.0f / (float)D1);
    float q = 0.0f;
    #pragma unroll
    for (int c = 0; c < 4; c++) { float d = v[c] - mu; q += d * d; }
    float var = blockReduceSum(q, red) * (1.0f / (float)D1);
    float rs = rsqrtf(var + LN_EPS);
    __half* ah = Ah + (size_t)b * KC;
    #pragma unroll
    for (int c = 0; c < 4; c++) {
        int i = threadIdx.x + c * 256;
        float hn = (v[c] - mu) * rs * gamma[i] + beta[i];
        float h = hn * (1.0f / (1.0f + __expf(-hn)));
        float t = tanh_acc(h);
        float T1 = t, T2 = 2.f * t * t - 1.f;
        float T3 = 2.f * t * T2 - T1, T4 = 2.f * t * T3 - T2, T5 = 2.f * t * T4 - T3;
        ah[0 * D1 + i] = __float2half_rn(T1);
        ah[1 * D1 + i] = __float2half_rn(T2);
        ah[2 * D1 + i] = __float2half_rn(T3);
        ah[3 * D1 + i] = __float2half_rn(T4);
        ah[4 * D1 + i] = __float2half_rn(T5);
        ah[5 * D1 + i] = __float2half_rn(h);
    }
}

// ---------------- HMMA GEMM: C[M,N] = Ahi*(Whi+Wlo)^T + biasE --------------
// 2-term fp16 split over 2 K-segments; BM=128 BN=128 BK=64, 3-stage TMA pipe,
// mma.sync.m16n8k16 with f32 accumulators in registers.
#define SM_FULL(s)  (8u + 8u * (s))
#define SM_EMPTY(s) (40u + 8u * (s))
#define SM_A(s)     (1024u + (s) * STAGE_BYTES)
#define SM_B(s)     (1024u + (s) * STAGE_BYTES + 16384u)

__global__ __launch_bounds__(256, 2)
void kan_gemm_kernel(const __grid_constant__ CUtensorMap tma_ahi,
                     const __grid_constant__ CUtensorMap tma_w,
                     const float* __restrict__ biasE,
                     float* __restrict__ C, int ldc) {
    extern __shared__ __align__(1024) char smem[];
    uint32_t sb = smem_u32(smem);
    int tid = threadIdx.x;
    int wid = tid >> 5, lane = tid & 31;
    int m_w = (wid & 3) * 32;        // warp rows within BM
    int n_w = (wid >> 2) * 64;       // warp cols within BN

    if (tid == 0) {
        #pragma unroll
        for (int s = 0; s < STAGES; s++) {
            MBAR_INIT(sb + SM_FULL(s), 1);
            MBAR_INIT(sb + SM_EMPTY(s), 8);
        }
    }
    __syncthreads();

    const int m0 = blockIdx.y * BM;
    const int n0 = blockIdx.x * BN;

    // prologue: issue stages 0 and 1 (both within segment 0)
    if (tid == 0) {
        #pragma unroll
        for (int ti = 0; ti < STAGES - 1; ti++) {
            MBAR_EXPECT_TX(sb + SM_FULL(ti), STAGE_BYTES);
            tma2d(sb + SM_A(ti), &tma_ahi, ti * BK, m0, sb + SM_FULL(ti));
            tma2d(sb + SM_B(ti), &tma_w, ti * BK, n0, sb + SM_FULL(ti));
        }
    }

    float acc[2][8][4];
    #pragma unroll
    for (int mt = 0; mt < 2; mt++)
        #pragma unroll
        for (int nt = 0; nt < 8; nt++)
            #pragma unroll
            for (int j = 0; j < 4; j++) acc[mt][nt][j] = 0.0f;

    // per-thread ldmatrix addressing (SW128 swizzle: xor term constant/thread)
    int rbase = (lane & 7) + ((lane >> 3) & 1) * 8;
    int hb = ((lane >> 4) & 1) * 16;
    uint32_t xorv = (uint32_t)((lane & 7) << 4);
    uint32_t aoffA = (uint32_t)(m_w + rbase) * 128u;
    uint32_t aoffB = (uint32_t)(n_w + rbase) * 128u;

    int s = 0, pf = 0, ep = 0;
    for (int t = 0; t < NT; t++) {
        MBAR_WAIT(sb + SM_FULL(s), pf);

        if (tid == 0 && t + STAGES - 1 < NT) {
            int ti = t + STAGES - 1;
            int sp = ti % STAGES;
            if (ti >= STAGES) {
                MBAR_WAIT_RELAXED(sb + SM_EMPTY(sp), ep);
                if (sp == STAGES - 1) ep ^= 1;
            }
            MBAR_EXPECT_TX(sb + SM_FULL(sp), STAGE_BYTES);
            int seg = ti / SEGI;
            int tk = (ti - seg * SEGI) * BK;
            int wx = (seg == 1) ? (KC + tk) : tk;
            tma2d(sb + SM_A(sp), &tma_ahi, tk, m0, sb + SM_FULL(sp));
            tma2d(sb + SM_B(sp), &tma_w, wx, n0, sb + SM_FULL(sp));
        }

        uint32_t sA = sb + SM_A(s);
        uint32_t sBt = sb + SM_B(s);
        #pragma unroll
        for (int ks = 0; ks < 4; ks++) {
            uint32_t col = ((uint32_t)(ks * 32 + hb)) ^ xorv;
            uint32_t a[2][4];
            ldsm4(a[0], sA + aoffA + col);
            ldsm4(a[1], sA + aoffA + 2048u + col);
            uint32_t b[8][2];
            #pragma unroll
            for (int g = 0; g < 4; g++) {
                uint32_t r[4];
                ldsm4(r, sBt + aoffB + (uint32_t)g * 2048u + col);
                b[2 * g][0] = r[0]; b[2 * g][1] = r[2];
                b[2 * g + 1][0] = r[1]; b[2 * g + 1][1] = r[3];
            }
            #pragma unroll
            for (int mt = 0; mt < 2; mt++)
                #pragma unroll
                for (int nt = 0; nt < 8; nt++)
                    mma16816(acc[mt][nt], a[mt], b[nt]);
        }
        if (lane == 0) MBAR_ARRIVE(sb + SM_EMPTY(s));
        s++;
        if (s == STAGES) { s = 0; pf ^= 1; }
    }

    // epilogue: register fragments -> global, + bias
    const float* bptr = biasE + n0 + n_w;
    #pragma unroll
    for (int mt = 0; mt < 2; mt++) {
        int r0 = m0 + m_w + mt * 16 + (lane >> 2);
        float* c0 = C + (size_t)r0 * ldc + n0 + n_w;
        float* c1 = c0 + 8 * (size_t)ldc;
        #pragma unroll
        for (int nt = 0; nt < 8; nt++) {
            int cidx = nt * 8 + (lane & 3) * 2;
            float bx = bptr[cidx], by = bptr[cidx + 1];
            float2 v0 = make_float2(acc[mt][nt][0] + bx, acc[mt][nt][1] + by);
            float2 v1 = make_float2(acc[mt][nt][2] + bx, acc[mt][nt][3] + by);
            *(float2*)(c0 + cidx) = v0;
            *(float2*)(c1 + cidx) = v1;
        }
    }
}

// ---------------- host ----------------
typedef CUresult (*PFN_encodeTiled)(CUtensorMap*, CUtensorMapDataType, cuuint32_t, void*,
                                    const cuuint64_t*, const cuuint64_t*, const cuuint32_t*, const cuuint32_t*,
                                    CUtensorMapInterleave, CUtensorMapSwizzle, CUtensorMapL2promotion,
                                    CUtensorMapFloatOOBfill);

static void encode_2d(PFN_encodeTiled enc, CUtensorMap* m, void* base,
                      uint64_t d0, uint64_t d1, uint32_t b0, uint32_t b1) {
    cuuint64_t dims[2] = {d0, d1};
    cuuint64_t strides[1] = {d0 * 2};   // fp16 row pitch
    cuuint32_t box[2] = {b0, b1};
    cuuint32_t es[2] = {1, 1};
    enc(m, CU_TENSOR_MAP_DATA_TYPE_FLOAT16, 2, base, dims, strides, box, es,
        CU_TENSOR_MAP_INTERLEAVE_NONE, CU_TENSOR_MAP_SWIZZLE_128B,
        CU_TENSOR_MAP_L2_PROMOTION_L2_128B, CU_TENSOR_MAP_FLOAT_OOB_FILL_NONE);
}

extern "C" void kernel_launch(void* const* d_in, const int* in_sizes, int n_in,
                              void* d_out, int out_size) {
    const float* x      = (const float*)d_in[0];
    const float* coeff1 = (const float*)d_in[1];
    const float* basew1 = (const float*)d_in[2];
    const float* bias1  = (const float*)d_in[3];
    const float* gamma  = (const float*)d_in[4];
    const float* beta   = (const float*)d_in[5];
    const float* coeff2 = (const float*)d_in[6];
    const float* basew2 = (const float*)d_in[7];
    const float* bias2  = (const float*)d_in[8];

    int B = in_sizes[0] / D0;

    void *pAh, *pW1, *pW2, *pB1, *pB2, *pY1;
    cudaGetSymbolAddress(&pAh, g_Ahi);
    cudaGetSymbolAddress(&pW1, g_W1);
    cudaGetSymbolAddress(&pW2, g_W2);
    cudaGetSymbolAddress(&pB1, g_biasE1);
    cudaGetSymbolAddress(&pB2, g_biasE2);
    cudaGetSymbolAddress(&pY1, g_Y1);

    PFN_encodeTiled enc = nullptr;
    cudaDriverEntryPointQueryResult qr;
    cudaGetDriverEntryPointByVersion("cuTensorMapEncodeTiled", (void**)&enc, 12000,
                                     cudaEnableDefault, &qr);

    CUtensorMap tma_ahi, tma_w1, tma_w2;
    encode_2d(enc, &tma_ahi, pAh, KC, (uint64_t)B, BK, BM);
    encode_2d(enc, &tma_w1, pW1, K2X, D1, BK, BN);
    encode_2d(enc, &tma_w2, pW2, K2X, D2, BK, BN);

    cudaFuncSetAttribute(kan_gemm_kernel, cudaFuncAttributeMaxDynamicSharedMemorySize, SMEM_TOTAL);

    // prep
    pack_w_kernel<<<(D1 * 1024 + 255) / 256, 256>>>(coeff1, basew1, (__half*)pW1, D1);
    pack_w_kernel<<<(D2 * 1024 + 255) / 256, 256>>>(coeff2, basew2, (__half*)pW2, D2);
    bias_eff_kernel<<<D1, 256>>>(coeff1, bias1, (float*)pB1, D0);
    bias_eff_kernel<<<D2, 256>>>(coeff2, bias2, (float*)pB2, D1);

    // layer 1
    feat1_kernel<<<(B * D0 + 255) / 256, 256>>>(x, (__half*)pAh, B);
    kan_gemm_kernel<<<dim3(D1 / BN, B / BM), 256, SMEM_TOTAL>>>(
        tma_ahi, tma_w1, (const float*)pB1, (float*)pY1, D1);

    // LN + SiLU + layer-2 features
    ln_silu_feat_kernel<<<B, 256>>>((const float*)pY1, gamma, beta, (__half*)pAh);

    // layer 2 -> output
    kan_gemm_kernel<<<dim3(D2 / BN, B / BM), 256, SMEM_TOTAL>>>(
        tma_ahi, tma_w2, (const float*)pB2, (float*)d_out, D2);
}

// round 10
// speedup vs baseline: 8.1629x; 1.8583x over previous
#include <cuda_runtime.h>
#include <cuda.h>
#include <cuda_fp16.h>
#include <math.h>
#include <stdint.h>

// ---------------- problem dims ----------------
#define D0 1024
#define D1 1024
#define D2 512
#define DEG 5
#define KC 6144            // K = 6*1024
#define NT 96              // KC/BK
#define LN_EPS 1e-5f
#define BMAX 16384

#define BM 128
#define BN 128
#define BK 64
#define STAGES 3
#define STAGE_BYTES 32768          // 16KB A + 16KB B
#define SMEM_TOTAL (1024 + STAGES*STAGE_BYTES)

// ---------------- device scratch (no allocs allowed) ----------------
__device__ __half g_Ahi[(size_t)BMAX * KC];   // 201 MB
__device__ __half g_W1[(size_t)D1 * KC];
__device__ __half g_W2[(size_t)D2 * KC];
__device__ float g_biasE1[D1];
__device__ float g_biasE2[D2];
__device__ float g_Y1[(size_t)BMAX * D1];

// ---------------- PTX helpers (sm_90-level only; NO tcgen05) ----------------
__device__ __forceinline__ uint32_t smem_u32(const void* p) {
    uint32_t a;
    asm("{ .reg .u64 t; cvta.to.shared.u64 t, %1; cvt.u32.u64 %0, t; }" : "=r"(a) : "l"(p));
    return a;
}
#define MBAR_INIT(a, c) asm volatile("mbarrier.init.shared.b64 [%0], %1;" :: "r"(a), "r"(c) : "memory")
#define MBAR_EXPECT_TX(a, b) asm volatile("mbarrier.arrive.expect_tx.shared.b64 _, [%0], %1;" :: "r"(a), "r"(b) : "memory")
#define MBAR_ARRIVE(a) asm volatile("mbarrier.arrive.shared.b64 _, [%0];" :: "r"(a) : "memory")

#define MBAR_WAIT(addr, ph) do { \
    uint32_t _m = (addr), _p = (ph), _d; \
    asm volatile("{\n\t.reg .pred p;\n\tmbarrier.try_wait.parity.acquire.cta.shared::cta.b64 p, [%1], %2;\n\tselp.b32 %0, 1, 0, p;\n\t}" \
        : "=r"(_d) : "r"(_m), "r"(_p) : "memory"); \
    if (!_d) { asm volatile("{\n\t.reg .pred P1;\n\tWL_%=:\n\tmbarrier.try_wait.parity.acquire.cta.shared::cta.b64 P1, [%0], %1, 0x989680;\n\t@P1 bra.uni WD_%=;\n\tbra.uni WL_%=;\n\tWD_%=:\n\t}" \
        :: "r"(_m), "r"(_p) : "memory"); } \
} while (0)

#define MBAR_WAIT_RELAXED(addr, ph) do { \
    uint32_t _m = (addr), _p = (ph), _d; \
    asm volatile("{\n\t.reg .pred p;\n\tmbarrier.try_wait.parity.relaxed.cta.shared::cta.b64 p, [%1], %2, 0x989680;\n\tselp.b32 %0, 1, 0, p;\n\t}" \
        : "=r"(_d) : "r"(_m), "r"(_p) : "memory"); \
    if (!_d) { asm volatile("{\n\t.reg .pred P1;\n\tWL_%=:\n\tmbarrier.try_wait.parity.relaxed.cta.shared::cta.b64 P1, [%0], %1, 0x989680;\n\t@P1 bra.uni WD_%=;\n\tbra.uni WL_%=;\n\tWD_%=:\n\t}" \
        :: "r"(_m), "r"(_p) : "memory"); } \
} while (0)

__device__ __forceinline__ void tma2d(uint32_t dst, const CUtensorMap* map, int x, int y, uint32_t mbar) {
    asm volatile("cp.async.bulk.tensor.2d.shared::cta.global.tile.mbarrier::complete_tx::bytes [%0], [%1, {%2, %3}], [%4];"
        :: "r"(dst), "l"(map), "r"(x), "r"(y), "r"(mbar) : "memory");
}

__device__ __forceinline__ void ldsm4(uint32_t* r, uint32_t addr) {
    asm volatile("ldmatrix.sync.aligned.m8n8.x4.shared.b16 {%0,%1,%2,%3}, [%4];"
        : "=r"(r[0]), "=r"(r[1]), "=r"(r[2]), "=r"(r[3]) : "r"(addr));
}

__device__ __forceinline__ void mma16816(float* c, const uint32_t* a, const uint32_t* b) {
    asm volatile("mma.sync.aligned.m16n8k16.row.col.f32.f16.f16.f32 "
                 "{%0,%1,%2,%3},{%4,%5,%6,%7},{%8,%9},{%0,%1,%2,%3};"
        : "+f"(c[0]), "+f"(c[1]), "+f"(c[2]), "+f"(c[3])
        : "r"(a[0]), "r"(a[1]), "r"(a[2]), "r"(a[3]), "r"(b[0]), "r"(b[1]));
}

// ---------------- math helpers ----------------
__device__ __forceinline__ float tanh_acc(float x) {
    float ax = fminf(fabsf(x), 10.0f);
    float e = __expf(2.0f * ax);
    float r = (e - 1.0f) / (e + 1.0f);
    return copysignf(r, x);
}
__device__ __forceinline__ float blockReduceSum(float v, float* red) {
    int lane = threadIdx.x & 31, w = threadIdx.x >> 5;
    #pragma unroll
    for (int o = 16; o; o >>= 1) v += __shfl_xor_sync(0xffffffffu, v, o);
    __syncthreads();
    if (lane == 0) red[w] = v;
    __syncthreads();
    float t = (lane < (blockDim.x >> 5)) ? red[lane] : 0.0f;
    #pragma unroll
    for (int o = 4; o; o >>= 1) t += __shfl_xor_sync(0xffffffffu, t, o);
    return __shfl_sync(0xffffffffu, t, 0);
}

// ---------------- prep kernels ----------------
__global__ void pack_w_kernel(const float* __restrict__ coeff, const float* __restrict__ basew,
                              __half* __restrict__ W, int O) {
    int idx = blockIdx.x * blockDim.x + threadIdx.x;
    if (idx >= O * 1024) return;
    int o = idx >> 10, i = idx & 1023;
    const float* c = coeff + ((size_t)o * 1024 + i) * (DEG + 1);
    __half* w = W + (size_t)o * KC;
    #pragma unroll
    for (int k = 0; k < 5; k++) w[k * 1024 + i] = __float2half_rn(c[k + 1]);
    w[5 * 1024 + i] = __float2half_rn(basew[(size_t)o * 1024 + i]);
}

__global__ void bias_eff_kernel(const float* __restrict__ coeff, const float* __restrict__ bias,
                                float* __restrict__ be, int I) {
    __shared__ float red[32];
    int o = blockIdx.x;
    float s = 0.0f;
    for (int i = threadIdx.x; i < I; i += blockDim.x)
        s += coeff[((size_t)o * I + i) * (DEG + 1)];
    float tot = blockReduceSum(s, red);
    if (threadIdx.x == 0) be[o] = bias[o] + tot;
}

__global__ void feat1_kernel(const float* __restrict__ x, __half* __restrict__ Ah, int B) {
    int idx = blockIdx.x * blockDim.x + threadIdx.x;
    if (idx >= B * D0) return;
    int b = idx >> 10, i = idx & 1023;
    float t1 = tanh_acc(x[idx]);
    float t2 = tanh_acc(t1);
    float T1 = t2, T2 = 2.f * t2 * t2 - 1.f;
    float T3 = 2.f * t2 * T2 - T1, T4 = 2.f * t2 * T3 - T2, T5 = 2.f * t2 * T4 - T3;
    __half* ah = Ah + (size_t)b * KC;
    ah[0 * D0 + i] = __float2half_rn(T1);
    ah[1 * D0 + i] = __float2half_rn(T2);
    ah[2 * D0 + i] = __float2half_rn(T3);
    ah[3 * D0 + i] = __float2half_rn(T4);
    ah[4 * D0 + i] = __float2half_rn(T5);
    ah[5 * D0 + i] = __float2half_rn(t1);
}

__global__ void ln_silu_feat_kernel(const float* __restrict__ Y,
                                    const float* __restrict__ gamma, const float* __restrict__ beta,
                                    __half* __restrict__ Ah) {
    __shared__ float red[32];
    int b = blockIdx.x;
    const float* y = Y + (size_t)b * D1;
    float v[4];
    #pragma unroll
    for (int c = 0; c < 4; c++) v[c] = y[threadIdx.x + c * 256];
    float mu = blockReduceSum(v[0] + v[1] + v[2] + v[3], red) * (1.0f / (float)D1);
    float q = 0.0f;
    #pragma unroll
    for (int c = 0; c < 4; c++) { float d = v[c] - mu; q += d * d; }
    float var = blockReduceSum(q, red) * (1.0f / (float)D1);
    float rs = rsqrtf(var + LN_EPS);
    __half* ah = Ah + (size_t)b * KC;
    #pragma unroll
    for (int c = 0; c < 4; c++) {
        int i = threadIdx.x + c * 256;
        float hn = (v[c] - mu) * rs * gamma[i] + beta[i];
        float h = hn * (1.0f / (1.0f + __expf(-hn)));
        float t = tanh_acc(h);
        float T1 = t, T2 = 2.f * t * t - 1.f;
        float T3 = 2.f * t * T2 - T1, T4 = 2.f * t * T3 - T2, T5 = 2.f * t * T4 - T3;
        ah[0 * D1 + i] = __float2half_rn(T1);
        ah[1 * D1 + i] = __float2half_rn(T2);
        ah[2 * D1 + i] = __float2half_rn(T3);
        ah[3 * D1 + i] = __float2half_rn(T4);
        ah[4 * D1 + i] = __float2half_rn(T5);
        ah[5 * D1 + i] = __float2half_rn(h);
    }
}

// ---------------- HMMA GEMM: C[M,N] = A*W^T + biasE ------------------------
// Pure fp16 operands, f32 accum; BM=128 BN=128 BK=64, 3-stage TMA pipe.
#define SM_FULL(s)  (8u + 8u * (s))
#define SM_EMPTY(s) (40u + 8u * (s))
#define SM_A(s)     (1024u + (s) * STAGE_BYTES)
#define SM_B(s)     (1024u + (s) * STAGE_BYTES + 16384u)

__global__ __launch_bounds__(256, 2)
void kan_gemm_kernel(const __grid_constant__ CUtensorMap tma_a,
                     const __grid_constant__ CUtensorMap tma_w,
                     const float* __restrict__ biasE,
                     float* __restrict__ C, int ldc) {
    extern __shared__ __align__(1024) char smem[];
    uint32_t sb = smem_u32(smem);
    int tid = threadIdx.x;
    int wid = tid >> 5, lane = tid & 31;
    int m_w = (wid & 3) * 32;        // warp rows within BM
    int n_w = (wid >> 2) * 64;       // warp cols within BN

    if (tid == 0) {
        #pragma unroll
        for (int s = 0; s < STAGES; s++) {
            MBAR_INIT(sb + SM_FULL(s), 1);
            MBAR_INIT(sb + SM_EMPTY(s), 8);
        }
    }
    __syncthreads();

    const int m0 = blockIdx.y * BM;
    const int n0 = blockIdx.x * BN;

    // prologue: issue stages 0 and 1
    if (tid == 0) {
        #pragma unroll
        for (int ti = 0; ti < STAGES - 1; ti++) {
            MBAR_EXPECT_TX(sb + SM_FULL(ti), STAGE_BYTES);
            tma2d(sb + SM_A(ti), &tma_a, ti * BK, m0, sb + SM_FULL(ti));
            tma2d(sb + SM_B(ti), &tma_w, ti * BK, n0, sb + SM_FULL(ti));
        }
    }

    float acc[2][8][4];
    #pragma unroll
    for (int mt = 0; mt < 2; mt++)
        #pragma unroll
        for (int nt = 0; nt < 8; nt++)
            #pragma unroll
            for (int j = 0; j < 4; j++) acc[mt][nt][j] = 0.0f;

    // per-thread ldmatrix addressing (SW128 swizzle: xor term constant/thread)
    int rbase = (lane & 7) + ((lane >> 3) & 1) * 8;
    int hb = ((lane >> 4) & 1) * 16;
    uint32_t xorv = (uint32_t)((lane & 7) << 4);
    uint32_t aoffA = (uint32_t)(m_w + rbase) * 128u;
    uint32_t aoffB = (uint32_t)(n_w + rbase) * 128u;

    int s = 0, pf = 0, ep = 0;
    for (int t = 0; t < NT; t++) {
        MBAR_WAIT(sb + SM_FULL(s), pf);

        if (tid == 0 && t + STAGES - 1 < NT) {
            int ti = t + STAGES - 1;
            int sp = ti % STAGES;
            if (ti >= STAGES) {
                MBAR_WAIT_RELAXED(sb + SM_EMPTY(sp), ep);
                if (sp == STAGES - 1) ep ^= 1;
            }
            MBAR_EXPECT_TX(sb + SM_FULL(sp), STAGE_BYTES);
            int tk = ti * BK;
            tma2d(sb + SM_A(sp), &tma_a, tk, m0, sb + SM_FULL(sp));
            tma2d(sb + SM_B(sp), &tma_w, tk, n0, sb + SM_FULL(sp));
        }

        uint32_t sA = sb + SM_A(s);
        uint32_t sBt = sb + SM_B(s);
        #pragma unroll
        for (int ks = 0; ks < 4; ks++) {
            uint32_t col = ((uint32_t)(ks * 32 + hb)) ^ xorv;
            uint32_t a[2][4];
            ldsm4(a[0], sA + aoffA + col);
            ldsm4(a[1], sA + aoffA + 2048u + col);
            uint32_t b[8][2];
            #pragma unroll
            for (int g = 0; g < 4; g++) {
                uint32_t r[4];
                ldsm4(r, sBt + aoffB + (uint32_t)g * 2048u + col);
                b[2 * g][0] = r[0]; b[2 * g][1] = r[2];
                b[2 * g + 1][0] = r[1]; b[2 * g + 1][1] = r[3];
            }
            #pragma unroll
            for (int mt = 0; mt < 2; mt++)
                #pragma unroll
                for (int nt = 0; nt < 8; nt++)
                    mma16816(acc[mt][nt], a[mt], b[nt]);
        }
        if (lane == 0) MBAR_ARRIVE(sb + SM_EMPTY(s));
        s++;
        if (s == STAGES) { s = 0; pf ^= 1; }
    }

    // epilogue: register fragments -> global, + bias
    const float* bptr = biasE + n0 + n_w;
    #pragma unroll
    for (int mt = 0; mt < 2; mt++) {
        int r0 = m0 + m_w + mt * 16 + (lane >> 2);
        float* c0 = C + (size_t)r0 * ldc + n0 + n_w;
        float* c1 = c0 + 8 * (size_t)ldc;
        #pragma unroll
        for (int nt = 0; nt < 8; nt++) {
            int cidx = nt * 8 + (lane & 3) * 2;
            float bx = bptr[cidx], by = bptr[cidx + 1];
            float2 v0 = make_float2(acc[mt][nt][0] + bx, acc[mt][nt][1] + by);
            float2 v1 = make_float2(acc[mt][nt][2] + bx, acc[mt][nt][3] + by);
            *(float2*)(c0 + cidx) = v0;
            *(float2*)(c1 + cidx) = v1;
        }
    }
}

// ---------------- host ----------------
typedef CUresult (*PFN_encodeTiled)(CUtensorMap*, CUtensorMapDataType, cuuint32_t, void*,
                                    const cuuint64_t*, const cuuint64_t*, const cuuint32_t*, const cuuint32_t*,
                                    CUtensorMapInterleave, CUtensorMapSwizzle, CUtensorMapL2promotion,
                                    CUtensorMapFloatOOBfill);

static void encode_2d(PFN_encodeTiled enc, CUtensorMap* m, void* base,
                      uint64_t d0, uint64_t d1, uint32_t b0, uint32_t b1) {
    cuuint64_t dims[2] = {d0, d1};
    cuuint64_t strides[1] = {d0 * 2};   // fp16 row pitch
    cuuint32_t box[2] = {b0, b1};
    cuuint32_t es[2] = {1, 1};
    enc(m, CU_TENSOR_MAP_DATA_TYPE_FLOAT16, 2, base, dims, strides, box, es,
        CU_TENSOR_MAP_INTERLEAVE_NONE, CU_TENSOR_MAP_SWIZZLE_128B,
        CU_TENSOR_MAP_L2_PROMOTION_L2_128B, CU_TENSOR_MAP_FLOAT_OOB_FILL_NONE);
}

extern "C" void kernel_launch(void* const* d_in, const int* in_sizes, int n_in,
                              void* d_out, int out_size) {
    const float* x      = (const float*)d_in[0];
    const float* coeff1 = (const float*)d_in[1];
    const float* basew1 = (const float*)d_in[2];
    const float* bias1  = (const float*)d_in[3];
    const float* gamma  = (const float*)d_in[4];
    const float* beta   = (const float*)d_in[5];
    const float* coeff2 = (const float*)d_in[6];
    const float* basew2 = (const float*)d_in[7];
    const float* bias2  = (const float*)d_in[8];

    int B = in_sizes[0] / D0;

    void *pAh, *pW1, *pW2, *pB1, *pB2, *pY1;
    cudaGetSymbolAddress(&pAh, g_Ahi);
    cudaGetSymbolAddress(&pW1, g_W1);
    cudaGetSymbolAddress(&pW2, g_W2);
    cudaGetSymbolAddress(&pB1, g_biasE1);
    cudaGetSymbolAddress(&pB2, g_biasE2);
    cudaGetSymbolAddress(&pY1, g_Y1);

    PFN_encodeTiled enc = nullptr;
    cudaDriverEntryPointQueryResult qr;
    cudaGetDriverEntryPointByVersion("cuTensorMapEncodeTiled", (void**)&enc, 12000,
                                     cudaEnableDefault, &qr);

    CUtensorMap tma_a, tma_w1, tma_w2;
    encode_2d(enc, &tma_a, pAh, KC, (uint64_t)B, BK, BM);
    encode_2d(enc, &tma_w1, pW1, KC, D1, BK, BN);
    encode_2d(enc, &tma_w2, pW2, KC, D2, BK, BN);

    cudaFuncSetAttribute(kan_gemm_kernel, cudaFuncAttributeMaxDynamicSharedMemorySize, SMEM_TOTAL);

    // prep
    pack_w_kernel<<<(D1 * 1024 + 255) / 256, 256>>>(coeff1, basew1, (__half*)pW1, D1);
    pack_w_kernel<<<(D2 * 1024 + 255) / 256, 256>>>(coeff2, basew2, (__half*)pW2, D2);
    bias_eff_kernel<<<D1, 256>>>(coeff1, bias1, (float*)pB1, D0);
    bias_eff_kernel<<<D2, 256>>>(coeff2, bias2, (float*)pB2, D1);

    // layer 1
    feat1_kernel<<<(B * D0 + 255) / 256, 256>>>(x, (__half*)pAh, B);
    kan_gemm_kernel<<<dim3(D1 / BN, B / BM), 256, SMEM_TOTAL>>>(
        tma_a, tma_w1, (const float*)pB1, (float*)pY1, D1);

    // LN + SiLU + layer-2 features
    ln_silu_feat_kernel<<<B, 256>>>((const float*)pY1, gamma, beta, (__half*)pAh);

    // layer 2 -> output
    kan_gemm_kernel<<<dim3(D2 / BN, B / BM), 256, SMEM_TOTAL>>>(
        tma_a, tma_w2, (const float*)pB2, (float*)d_out, D2);
}